// round 11
// baseline (speedup 1.0000x reference)
#include <cuda_runtime.h>
#include <cuda_fp16.h>
#include <cstdint>
#include <math.h>

#define NREL   3
#define NNODES 65536
#define FEAT   512
#define EMB    512
#define BK     32             // k halves per chunk
#define NCHUNK (FEAT/BK)      // 16
#define STAGES 3
#define ASTRIDE 520           // halves per resident-A row (conflict-free for ldmatrix)
#define A_BYTES (128 * ASTRIDE * 2)        // 133120
#define WSTG    10240                      // 128 rows * 40 halves * 2
#define SM_W    A_BYTES                    // W stage ring base (Ts aliases this)
#define SM_US   (A_BYTES + STAGES * WSTG)  // 163840 : u vectors (4 KB)
#define SM_DOTS (SM_US + 4096)             // dots[4][2][4] floats
#define SM_BS   (SM_DOTS + 128)            // bsums[4][3] floats
#define SM_TOTAL (SM_BS + 64)              // 168032 -> pad

// ---- scratch (static device globals; no allocations allowed) ----
__device__ __half  g_Wh[(size_t)EMB * FEAT];       // fp16 weight copy
__device__ float   g_u[2*EMB];
__device__ float   g_up[64 * 1024];                // prep partials
__device__ double  g_s[NREL];

__device__ __forceinline__ uint32_t smem_u32(const void* p) {
    uint32_t a;
    asm("{ .reg .u64 t; cvta.to.shared.u64 t, %1; cvt.u32.u64 %0, t; }" : "=r"(a) : "l"(p));
    return a;
}

__device__ __forceinline__ void mma_f16(float c[4], const unsigned a[4], const unsigned b[2]) {
    asm volatile(
        "mma.sync.aligned.m16n8k16.row.col.f32.f16.f16.f32 "
        "{%0,%1,%2,%3}, {%4,%5,%6,%7}, {%8,%9}, {%0,%1,%2,%3};\n"
        : "+f"(c[0]), "+f"(c[1]), "+f"(c[2]), "+f"(c[3])
        : "r"(a[0]), "r"(a[1]), "r"(a[2]), "r"(a[3]), "r"(b[0]), "r"(b[1]));
}

__device__ __forceinline__ void ldsm4(unsigned r[4], uint32_t addr) {
    asm volatile("ldmatrix.sync.aligned.m8n8.x4.shared.b16 {%0,%1,%2,%3}, [%4];"
        : "=r"(r[0]), "=r"(r[1]), "=r"(r[2]), "=r"(r[3]) : "r"(addr));
}

__device__ __forceinline__ void cpasync16(uint32_t smem, const void* g) {
    asm volatile("cp.async.cg.shared.global [%0], [%1], 16;" :: "r"(smem), "l"(g));
}
#define CP_COMMIT() asm volatile("cp.async.commit_group;" ::: "memory")
#define CP_WAIT(n)  asm volatile("cp.async.wait_group %0;" :: "n"(n) : "memory")

// ---- kernel 0a: W -> fp16 + partial u sums (8 e-rows per block) ----
__global__ __launch_bounds__(512)
void wprep_kernel(const float* __restrict__ W, const float* __restrict__ a) {
    int f = threadIdx.x;          // 0..511
    int b = blockIdx.x;           // 0..63
    int e0 = b * 8;
    float sc = 0.f, sn = 0.f;
    #pragma unroll
    for (int j = 0; j < 8; ++j) {
        float w = W[(size_t)(e0 + j) * FEAT + f];
        g_Wh[(size_t)(e0 + j) * FEAT + f] = __float2half_rn(w);
        sc += w * a[e0 + j];
        sn += w * a[EMB + e0 + j];
    }
    g_up[b * 1024 + f]       = sc;
    g_up[b * 1024 + 512 + f] = sn;
}

__global__ void prep2_kernel() {
    int i = blockIdx.x * 256 + threadIdx.x;   // 0..1023
    float s = 0.f;
    #pragma unroll
    for (int b = 0; b < 64; ++b) s += g_up[b * 1024 + i];
    g_u[i] = s;
    if (i < NREL) g_s[i] = 0.0;
}

// ---- fused kernel: per-128-node block: attention+mix into resident smem A,
//      then fp16 mma.sync GEMM vs all 512 embed rows (4 col-blocks), fused
//      relu + transpose epilogue. One CTA per SM (168 KB smem). ----
__global__ void __launch_bounds__(256, 1)
fused_kernel(const float* __restrict__ selfF, const float* __restrict__ neighF,
             float* __restrict__ out) {
    extern __shared__ __align__(16) char sm[];
    const uint32_t base = smem_u32(sm);
    const int tid  = threadIdx.x;
    const int wid  = tid >> 5, lane = tid & 31;

    const size_t rowBlk = (size_t)blockIdx.x * 128;   // node base

    float* us    = (float*)(sm + SM_US);       // 2*512 floats
    float* dots  = (float*)(sm + SM_DOTS);     // [4][2][4]
    float* bsums = (float*)(sm + SM_BS);       // [4][3]

    // stage u vectors (256 float4)
    ((float4*)us)[tid] = ((const float4*)g_u)[tid];
    __syncthreads();

    // ================= Phase 1: attention + mix into resident A =================
    const int nl   = wid >> 1;    // node-in-group 0..3
    const int half = wid & 1;     // feature half
    float sa0 = 0.f, sa1 = 0.f, sa2 = 0.f;   // owner-thread attention sums

    #pragma unroll 1
    for (int it = 0; it < 32; ++it) {
        const int nloc = it * 4 + nl;           // node local 0..127
        const size_t n = rowBlk + nloc;

        const float4* sp  = (const float4*)(selfF + n * FEAT);
        const float4* np0 = (const float4*)(neighF + ((size_t)0 * NNODES + n) * FEAT);
        const float4* np1 = (const float4*)(neighF + ((size_t)1 * NNODES + n) * FEAT);
        const float4* np2 = (const float4*)(neighF + ((size_t)2 * NNODES + n) * FEAT);

        float4 s[2], n0[2], n1[2], n2[2];
        #pragma unroll
        for (int j = 0; j < 2; ++j) {
            int idx = half * 64 + lane + 32 * j;
            s[j]  = sp[idx];
            n0[j] = np0[idx];
            n1[j] = np1[idx];
            n2[j] = np2[idx];
        }

        float ec = 0.f, e0 = 0.f, e1 = 0.f, e2 = 0.f;
        #pragma unroll
        for (int j = 0; j < 2; ++j) {
            int idx = half * 64 + lane + 32 * j;
            float4 uc = ((const float4*)us)[idx];
            float4 un = ((const float4*)us)[128 + idx];
            ec += s[j].x*uc.x + s[j].y*uc.y + s[j].z*uc.z + s[j].w*uc.w;
            e0 += n0[j].x*un.x + n0[j].y*un.y + n0[j].z*un.z + n0[j].w*un.w;
            e1 += n1[j].x*un.x + n1[j].y*un.y + n1[j].z*un.z + n1[j].w*un.w;
            e2 += n2[j].x*un.x + n2[j].y*un.y + n2[j].z*un.z + n2[j].w*un.w;
        }
        #pragma unroll
        for (int o = 16; o; o >>= 1) {
            ec += __shfl_xor_sync(0xffffffffu, ec, o);
            e0 += __shfl_xor_sync(0xffffffffu, e0, o);
            e1 += __shfl_xor_sync(0xffffffffu, e1, o);
            e2 += __shfl_xor_sync(0xffffffffu, e2, o);
        }
        if (lane == 0) {
            dots[(nl * 2 + half) * 4 + 0] = ec;
            dots[(nl * 2 + half) * 4 + 1] = e0;
            dots[(nl * 2 + half) * 4 + 2] = e1;
            dots[(nl * 2 + half) * 4 + 3] = e2;
        }
        __syncthreads();

        float fec = dots[(nl * 2) * 4 + 0] + dots[(nl * 2 + 1) * 4 + 0];
        float fe0 = dots[(nl * 2) * 4 + 1] + dots[(nl * 2 + 1) * 4 + 1];
        float fe1 = dots[(nl * 2) * 4 + 2] + dots[(nl * 2 + 1) * 4 + 2];
        float fe2 = dots[(nl * 2) * 4 + 3] + dots[(nl * 2 + 1) * 4 + 3];

        float v0 = fec + fe0, v1 = fec + fe1, v2 = fec + fe2;
        v0 = v0 > 0.f ? v0 : 0.2f * v0;
        v1 = v1 > 0.f ? v1 : 0.2f * v1;
        v2 = v2 > 0.f ? v2 : 0.2f * v2;
        float mx = fmaxf(v0, fmaxf(v1, v2));
        float x0 = expf(v0 - mx), x1 = expf(v1 - mx), x2 = expf(v2 - mx);
        float inv = 1.f / (x0 + x1 + x2);
        float a0 = x0 * inv, a1 = x1 * inv, a2 = x2 * inv;

        // mix -> resident A (fp16, stride ASTRIDE halves)
        #pragma unroll
        for (int j = 0; j < 2; ++j) {
            int idx = half * 64 + lane + 32 * j;    // float4 index within row
            float4 m;
            m.x = s[j].x + a0*n0[j].x + a1*n1[j].x + a2*n2[j].x;
            m.y = s[j].y + a0*n0[j].y + a1*n1[j].y + a2*n2[j].y;
            m.z = s[j].z + a0*n0[j].z + a1*n1[j].z + a2*n2[j].z;
            m.w = s[j].w + a0*n0[j].w + a1*n1[j].w + a2*n2[j].w;
            __half2 h0 = __floats2half2_rn(m.x, m.y);
            __half2 h1 = __floats2half2_rn(m.z, m.w);
            uint2 p;
            p.x = *(unsigned*)&h0;  p.y = *(unsigned*)&h1;
            *(uint2*)(sm + (nloc * ASTRIDE + idx * 4) * 2) = p;
        }

        if (half == 0 && lane == 0) { sa0 += a0; sa1 += a1; sa2 += a2; }
        __syncthreads();   // protect dots WAR for next iteration
    }

    // deterministic CTA attention-sum reduction
    if (half == 0 && lane == 0) {
        bsums[nl * 3 + 0] = sa0;
        bsums[nl * 3 + 1] = sa1;
        bsums[nl * 3 + 2] = sa2;
    }
    __syncthreads();
    if (tid == 0) {
        float t0 = 0.f, t1 = 0.f, t2 = 0.f;
        #pragma unroll
        for (int q = 0; q < 4; ++q) {
            t0 += bsums[q * 3 + 0];
            t1 += bsums[q * 3 + 1];
            t2 += bsums[q * 3 + 2];
        }
        atomicAdd(&g_s[0], (double)t0);
        atomicAdd(&g_s[1], (double)t1);
        atomicAdd(&g_s[2], (double)t2);
    }

    // ================= Phase 2: GEMM vs W, 4 embed col-blocks =================
    const int wm = wid >> 2;     // 0..1 -> node rows wm*64
    const int wn = wid & 3;      // 0..3 -> embed cols wn*32 (within cb)
    const int g  = lane >> 2;
    const int tg = lane & 3;

    const int r0  = tid >> 2;          // 0..63
    const int kq8 = (tid & 3) * 8;
    const uint32_t st0 = (uint32_t)(r0 * 40 + kq8) * 2;
    const uint32_t st1 = st0 + 64 * 80;

    const uint32_t laneA = (uint32_t)(((lane & 15) * ASTRIDE + (lane >> 4) * 8) * 2);
    const uint32_t laneB = (uint32_t)((((lane & 7) + ((lane >> 4) << 3)) * 40
                                       + (((lane >> 3) & 1) << 3)) * 2);
    const uint32_t wbase = base + SM_W;
    float* Ts = (float*)(sm + SM_W);   // epilogue transpose buffer (aliases ring)

    #pragma unroll 1
    for (int cb = 0; cb < 4; ++cb) {
        const int colBlk = cb * 128;
        const __half* gW0 = g_Wh + (size_t)(colBlk + r0) * FEAT + kq8;
        const __half* gW1 = g_Wh + (size_t)(colBlk + r0 + 64) * FEAT + kq8;

        __syncthreads();   // ring region free (A done / prior epilogue done)

        // prologue: issue 2 chunks
        #pragma unroll
        for (int t = 0; t < STAGES - 1; ++t) {
            uint32_t sB = wbase + t * WSTG;
            int k0 = t * BK;
            cpasync16(sB + st0, gW0 + k0);
            cpasync16(sB + st1, gW1 + k0);
            CP_COMMIT();
        }

        float acc[4][4][4];
        #pragma unroll
        for (int i = 0; i < 4; ++i)
            #pragma unroll
            for (int j = 0; j < 4; ++j)
                #pragma unroll
                for (int q = 0; q < 4; ++q) acc[i][j][q] = 0.f;

        int slot = 0;
        #pragma unroll 1
        for (int t = 0; t < NCHUNK; ++t) {
            CP_WAIT(STAGES - 2);
            __syncthreads();

            const uint32_t uB = wbase + slot * WSTG;

            const int tn = t + STAGES - 1;
            if (tn < NCHUNK) {
                int ns = slot + (STAGES - 1);  if (ns >= STAGES) ns -= STAGES;
                uint32_t sB = wbase + ns * WSTG;
                int k0 = tn * BK;
                cpasync16(sB + st0, gW0 + k0);
                cpasync16(sB + st1, gW1 + k0);
            }
            CP_COMMIT();

            unsigned af[2][4][4], bf[2][4][2];
            #pragma unroll
            for (int kk = 0; kk < 2; ++kk) {
                #pragma unroll
                for (int mt = 0; mt < 4; ++mt) {
                    uint32_t addr = base + laneA
                        + (uint32_t)(((wm * 64 + mt * 16) * ASTRIDE + t * BK + kk * 16) * 2);
                    ldsm4(af[kk][mt], addr);
                }
                #pragma unroll
                for (int p = 0; p < 2; ++p) {
                    unsigned r[4];
                    uint32_t addr = uB + laneB
                        + (uint32_t)((((wn * 32 + p * 16) * 40) + kk * 16) * 2);
                    ldsm4(r, addr);
                    bf[kk][2*p  ][0] = r[0];  bf[kk][2*p  ][1] = r[1];
                    bf[kk][2*p+1][0] = r[2];  bf[kk][2*p+1][1] = r[3];
                }
            }
            #pragma unroll
            for (int kk = 0; kk < 2; ++kk)
                #pragma unroll
                for (int mt = 0; mt < 4; ++mt)
                    #pragma unroll
                    for (int nt = 0; nt < 4; ++nt)
                        mma_f16(acc[mt][nt], af[kk][mt], bf[kk][nt]);

            if (++slot == STAGES) slot = 0;
        }

        // epilogue cb: relu + transpose -> out[e][n] (Ts aliases ring; all
        // W data groups are complete by the final CP_WAIT above)
        #pragma unroll 1
        for (int c = 0; c < 4; ++c) {
            __syncthreads();
            if (wn == c) {
                #pragma unroll
                for (int mt = 0; mt < 4; ++mt) {
                    #pragma unroll
                    for (int nt = 0; nt < 4; ++nt) {
                        int colL = nt * 8 + 2 * tg;
                        int rowL = wm * 64 + mt * 16 + g;
                        float q0 = acc[mt][nt][0], q1 = acc[mt][nt][1];
                        float q2 = acc[mt][nt][2], q3 = acc[mt][nt][3];
                        Ts[(colL    ) * 132 + rowL    ] = q0 > 0.f ? q0 : 0.f;
                        Ts[(colL + 1) * 132 + rowL    ] = q1 > 0.f ? q1 : 0.f;
                        Ts[(colL    ) * 132 + rowL + 8] = q2 > 0.f ? q2 : 0.f;
                        Ts[(colL + 1) * 132 + rowL + 8] = q3 > 0.f ? q3 : 0.f;
                    }
                }
            }
            __syncthreads();
            int el  = tid >> 3;
            int f4i = tid & 7;
            size_t obase = (size_t)(colBlk + c * 32 + el) * NNODES + rowBlk;
            #pragma unroll
            for (int j = 0; j < 4; ++j) {
                float4 v = *(const float4*)&Ts[el * 132 + j * 32 + f4i * 4];
                *(float4*)&out[obase + j * 32 + f4i * 4] = v;
            }
        }
    }
}

// ---- tail: softmax over 3 relation sums ----
__global__ void attout_kernel(float* __restrict__ out) {
    double s0 = g_s[0], s1 = g_s[1], s2 = g_s[2];
    double m = fmax(s0, fmax(s1, s2));
    double e0 = exp(s0 - m), e1 = exp(s1 - m), e2 = exp(s2 - m);
    double inv = 1.0 / (e0 + e1 + e2);
    size_t basei = (size_t)EMB * NNODES;
    out[basei + 0] = (float)(e0 * inv);
    out[basei + 1] = (float)(e1 * inv);
    out[basei + 2] = (float)(e2 * inv);
}

extern "C" void kernel_launch(void* const* d_in, const int* in_sizes, int n_in,
                              void* d_out, int out_size) {
    const float* selfF  = (const float*)d_in[0];
    const float* neighF = (const float*)d_in[1];
    const float* W      = (const float*)d_in[2];
    const float* a      = (const float*)d_in[3];
    float* out = (float*)d_out;

    cudaFuncSetAttribute(fused_kernel, cudaFuncAttributeMaxDynamicSharedMemorySize, SM_TOTAL);

    wprep_kernel<<<64, 512>>>(W, a);
    prep2_kernel<<<4, 256>>>();
    fused_kernel<<<NNODES / 128, 256, SM_TOTAL>>>(selfF, neighF, out);
    attout_kernel<<<1, 1>>>(out);
}

// round 12
// speedup vs baseline: 1.4727x; 1.4727x over previous
#include <cuda_runtime.h>
#include <cuda_fp16.h>
#include <cstdint>
#include <math.h>

#define NREL   3
#define NNODES 65536
#define FEAT   512
#define EMB    512
#define BK     32            // k halves per chunk
#define NCHUNK (FEAT/BK)     // 16
#define STAGES 4
#define STAGE_BYTES 20480    // A(10240) + B(10240), stride-40-half rows
#define SM_TOTAL (STAGES * STAGE_BYTES)   // 81920
#define NQ 4                 // pipeline quarters

// ---- scratch (static device globals; no allocations allowed) ----
__device__ __half  g_mixh[(size_t)NNODES * FEAT];  // 67 MB fp16 mixed features
__device__ __half  g_Wh[(size_t)EMB * FEAT];       // fp16 weight copy
__device__ float   g_u[2*EMB];
__device__ float   g_up[64 * 1024];                // prep partials
__device__ double  g_s[NREL];

__device__ __forceinline__ uint32_t smem_u32(const void* p) {
    uint32_t a;
    asm("{ .reg .u64 t; cvta.to.shared.u64 t, %1; cvt.u32.u64 %0, t; }" : "=r"(a) : "l"(p));
    return a;
}

__device__ __forceinline__ void mma_f16(float c[4], const unsigned a[4], const unsigned b[2]) {
    asm volatile(
        "mma.sync.aligned.m16n8k16.row.col.f32.f16.f16.f32 "
        "{%0,%1,%2,%3}, {%4,%5,%6,%7}, {%8,%9}, {%0,%1,%2,%3};\n"
        : "+f"(c[0]), "+f"(c[1]), "+f"(c[2]), "+f"(c[3])
        : "r"(a[0]), "r"(a[1]), "r"(a[2]), "r"(a[3]), "r"(b[0]), "r"(b[1]));
}

__device__ __forceinline__ void ldsm4(unsigned r[4], uint32_t addr) {
    asm volatile("ldmatrix.sync.aligned.m8n8.x4.shared.b16 {%0,%1,%2,%3}, [%4];"
        : "=r"(r[0]), "=r"(r[1]), "=r"(r[2]), "=r"(r[3]) : "r"(addr));
}

__device__ __forceinline__ void cpasync16(uint32_t smem, const void* g) {
    asm volatile("cp.async.cg.shared.global [%0], [%1], 16;" :: "r"(smem), "l"(g));
}
#define CP_COMMIT() asm volatile("cp.async.commit_group;" ::: "memory")
#define CP_WAIT(n)  asm volatile("cp.async.wait_group %0;" :: "n"(n) : "memory")

// ---- kernel 0a: W -> fp16 + partial u sums (8 e-rows per block) ----
__global__ __launch_bounds__(512)
void wprep_kernel(const float* __restrict__ W, const float* __restrict__ a) {
    int f = threadIdx.x;          // 0..511
    int b = blockIdx.x;           // 0..63
    int e0 = b * 8;
    float sc = 0.f, sn = 0.f;
    #pragma unroll
    for (int j = 0; j < 8; ++j) {
        float w = W[(size_t)(e0 + j) * FEAT + f];
        g_Wh[(size_t)(e0 + j) * FEAT + f] = __float2half_rn(w);
        sc += w * a[e0 + j];
        sn += w * a[EMB + e0 + j];
    }
    g_up[b * 1024 + f]       = sc;
    g_up[b * 1024 + 512 + f] = sn;
}

__global__ void prep2_kernel() {
    int i = blockIdx.x * 256 + threadIdx.x;   // 0..1023
    float s = 0.f;
    #pragma unroll
    for (int b = 0; b < 64; ++b) s += g_up[b * 1024 + i];
    g_u[i] = s;
    if (i < NREL) g_s[i] = 0.0;
}

// ---- kernel 1: per-node attention + feature mix (2 warps per node) ----
__global__ __launch_bounds__(256, 5)
void mix_kernel(const float* __restrict__ selfF, const float* __restrict__ neighF,
                int nbase) {
    __shared__ float us[2 * EMB];
    __shared__ float dots[4][2][4];
    __shared__ float bs[NREL];

    const int tid  = threadIdx.x;
    const int lane = tid & 31;
    const int wid  = tid >> 5;
    const int nl   = wid >> 1;
    const int half = wid & 1;
    const int n    = nbase + blockIdx.x * 4 + nl;

    ((float4*)us)[tid] = ((const float4*)g_u)[tid];
    if (tid < NREL) bs[tid] = 0.f;
    __syncthreads();

    const float4* sp  = (const float4*)(selfF + (size_t)n * FEAT);
    const float4* np0 = (const float4*)(neighF + ((size_t)0 * NNODES + n) * FEAT);
    const float4* np1 = (const float4*)(neighF + ((size_t)1 * NNODES + n) * FEAT);
    const float4* np2 = (const float4*)(neighF + ((size_t)2 * NNODES + n) * FEAT);

    float4 s[2], n0[2], n1[2], n2[2];
    #pragma unroll
    for (int j = 0; j < 2; ++j) {
        int idx = half * 64 + lane + 32 * j;
        s[j]  = sp[idx];
        n0[j] = np0[idx];
        n1[j] = np1[idx];
        n2[j] = np2[idx];
    }

    float ec = 0.f, e0 = 0.f, e1 = 0.f, e2 = 0.f;
    #pragma unroll
    for (int j = 0; j < 2; ++j) {
        int idx = half * 64 + lane + 32 * j;
        float4 uc = ((const float4*)us)[idx];
        float4 un = ((const float4*)us)[128 + idx];
        ec += s[j].x*uc.x + s[j].y*uc.y + s[j].z*uc.z + s[j].w*uc.w;
        e0 += n0[j].x*un.x + n0[j].y*un.y + n0[j].z*un.z + n0[j].w*un.w;
        e1 += n1[j].x*un.x + n1[j].y*un.y + n1[j].z*un.z + n1[j].w*un.w;
        e2 += n2[j].x*un.x + n2[j].y*un.y + n2[j].z*un.z + n2[j].w*un.w;
    }
    #pragma unroll
    for (int o = 16; o; o >>= 1) {
        ec += __shfl_xor_sync(0xffffffffu, ec, o);
        e0 += __shfl_xor_sync(0xffffffffu, e0, o);
        e1 += __shfl_xor_sync(0xffffffffu, e1, o);
        e2 += __shfl_xor_sync(0xffffffffu, e2, o);
    }
    if (lane == 0) {
        dots[nl][half][0] = ec;
        dots[nl][half][1] = e0;
        dots[nl][half][2] = e1;
        dots[nl][half][3] = e2;
    }
    __syncthreads();

    float fec = dots[nl][0][0] + dots[nl][1][0];
    float fe0 = dots[nl][0][1] + dots[nl][1][1];
    float fe1 = dots[nl][0][2] + dots[nl][1][2];
    float fe2 = dots[nl][0][3] + dots[nl][1][3];

    float v0 = fec + fe0, v1 = fec + fe1, v2 = fec + fe2;
    v0 = v0 > 0.f ? v0 : 0.2f * v0;
    v1 = v1 > 0.f ? v1 : 0.2f * v1;
    v2 = v2 > 0.f ? v2 : 0.2f * v2;
    float mx = fmaxf(v0, fmaxf(v1, v2));
    float x0 = expf(v0 - mx), x1 = expf(v1 - mx), x2 = expf(v2 - mx);
    float inv = 1.f / (x0 + x1 + x2);
    float a0 = x0 * inv, a1 = x1 * inv, a2 = x2 * inv;

    uint2* mp = (uint2*)(g_mixh + (size_t)n * FEAT);
    #pragma unroll
    for (int j = 0; j < 2; ++j) {
        int idx = half * 64 + lane + 32 * j;
        float4 m;
        m.x = s[j].x + a0*n0[j].x + a1*n1[j].x + a2*n2[j].x;
        m.y = s[j].y + a0*n0[j].y + a1*n1[j].y + a2*n2[j].y;
        m.z = s[j].z + a0*n0[j].z + a1*n1[j].z + a2*n2[j].z;
        m.w = s[j].w + a0*n0[j].w + a1*n1[j].w + a2*n2[j].w;
        __half2 h0 = __floats2half2_rn(m.x, m.y);
        __half2 h1 = __floats2half2_rn(m.z, m.w);
        uint2 p;
        p.x = *(unsigned*)&h0;  p.y = *(unsigned*)&h1;
        mp[idx] = p;
    }

    if (half == 0 && lane == 0) {
        atomicAdd(&bs[0], a0); atomicAdd(&bs[1], a1); atomicAdd(&bs[2], a2);
    }
    __syncthreads();
    if (tid < NREL) atomicAdd(&g_s[tid], (double)bs[tid]);
}

// ---- kernel 2: fp16 mma.sync GEMM; cp.async 4-stage ring + ldmatrix ----
// out[col][row] = relu( sum_k mix[row][k] * W[col][k] ); 8 warps 2m x 4n.
__global__ void __launch_bounds__(256, 2)
gemm_kernel(float* __restrict__ out, int ybase) {
    extern __shared__ __align__(16) char sm[];
    const int tid  = threadIdx.x;
    const int wid  = tid >> 5, lane = tid & 31;
    const int wm   = wid >> 2;   // 0..1
    const int wn   = wid & 3;    // 0..3
    const int g    = lane >> 2;
    const int tg   = lane & 3;

    const size_t rowBlk = (size_t)(ybase + blockIdx.y) * 128;   // nodes
    const int    colBlk = blockIdx.x * 128;                     // embed
    const __half* Aptr = g_mixh + rowBlk * FEAT;
    const __half* Bp   = g_Wh + (size_t)colBlk * FEAT;

    const uint32_t base = smem_u32(sm);

    const int r0  = tid >> 2;          // 0..63
    const int kq8 = (tid & 3) * 8;
    const uint32_t st0 = (uint32_t)(r0 * 40 + kq8) * 2;
    const uint32_t st1 = st0 + 64 * 40 * 2;

    const uint32_t laneA = (uint32_t)(((lane & 15) * 40 + (lane >> 4) * 8) * 2);
    const uint32_t laneB = (uint32_t)((((lane & 7) + ((lane >> 4) << 3)) * 40
                                       + (((lane >> 3) & 1) << 3)) * 2);

    const __half* gA0 = Aptr + (size_t)r0 * FEAT + kq8;
    const __half* gA1 = Aptr + (size_t)(r0 + 64) * FEAT + kq8;
    const __half* gB0 = Bp   + (size_t)r0 * FEAT + kq8;
    const __half* gB1 = Bp   + (size_t)(r0 + 64) * FEAT + kq8;

    // prologue: issue STAGES-1 chunks
    #pragma unroll
    for (int t = 0; t < STAGES - 1; ++t) {
        uint32_t sA = base + t * STAGE_BYTES;
        uint32_t sB = sA + 10240;
        int k0 = t * BK;
        cpasync16(sA + st0, gA0 + k0);
        cpasync16(sA + st1, gA1 + k0);
        cpasync16(sB + st0, gB0 + k0);
        cpasync16(sB + st1, gB1 + k0);
        CP_COMMIT();
    }

    float acc[4][4][4];
    #pragma unroll
    for (int i = 0; i < 4; ++i)
        #pragma unroll
        for (int j = 0; j < 4; ++j)
            #pragma unroll
            for (int q = 0; q < 4; ++q) acc[i][j][q] = 0.f;

    #pragma unroll 1
    for (int t = 0; t < NCHUNK; ++t) {
        CP_WAIT(STAGES - 2);
        __syncthreads();

        const int slot = t & (STAGES - 1);
        const uint32_t uA = base + slot * STAGE_BYTES;
        const uint32_t uB = uA + 10240;

        #pragma unroll
        for (int kk = 0; kk < 2; ++kk) {
            unsigned af[4][4], bf[4][2];
            #pragma unroll
            for (int mt = 0; mt < 4; ++mt) {
                uint32_t addr = uA + laneA
                              + (uint32_t)((((wm * 64 + mt * 16) * 40) + kk * 16) * 2);
                ldsm4(af[mt], addr);
            }
            #pragma unroll
            for (int p = 0; p < 2; ++p) {
                unsigned r[4];
                uint32_t addr = uB + laneB
                              + (uint32_t)((((wn * 32 + p * 16) * 40) + kk * 16) * 2);
                ldsm4(r, addr);
                bf[2*p  ][0] = r[0];  bf[2*p  ][1] = r[1];
                bf[2*p+1][0] = r[2];  bf[2*p+1][1] = r[3];
            }
            #pragma unroll
            for (int mt = 0; mt < 4; ++mt)
                #pragma unroll
                for (int nt = 0; nt < 4; ++nt)
                    mma_f16(acc[mt][nt], af[mt], bf[nt]);
        }

        const int tn = t + STAGES - 1;
        if (tn < NCHUNK) {
            const int ns = tn & (STAGES - 1);
            uint32_t sA = base + ns * STAGE_BYTES;
            uint32_t sB = sA + 10240;
            int k0 = tn * BK;
            cpasync16(sA + st0, gA0 + k0);
            cpasync16(sA + st1, gA1 + k0);
            cpasync16(sB + st0, gB0 + k0);
            cpasync16(sB + st1, gB1 + k0);
        }
        CP_COMMIT();
    }

    // epilogue: relu + transpose -> out[e][n]; Ts aliases the ring buffer
    float* Ts = (float*)sm;   // 32 x 132
    #pragma unroll 1
    for (int c = 0; c < 4; ++c) {
        __syncthreads();
        if (wn == c) {
            #pragma unroll
            for (int mt = 0; mt < 4; ++mt) {
                #pragma unroll
                for (int nt = 0; nt < 4; ++nt) {
                    int colL = nt * 8 + 2 * tg;
                    int rowL = wm * 64 + mt * 16 + g;
                    float q0 = acc[mt][nt][0], q1 = acc[mt][nt][1];
                    float q2 = acc[mt][nt][2], q3 = acc[mt][nt][3];
                    Ts[(colL    ) * 132 + rowL    ] = q0 > 0.f ? q0 : 0.f;
                    Ts[(colL + 1) * 132 + rowL    ] = q1 > 0.f ? q1 : 0.f;
                    Ts[(colL    ) * 132 + rowL + 8] = q2 > 0.f ? q2 : 0.f;
                    Ts[(colL + 1) * 132 + rowL + 8] = q3 > 0.f ? q3 : 0.f;
                }
            }
        }
        __syncthreads();
        int el  = tid >> 3;
        int f4i = tid & 7;
        size_t obase = (size_t)(colBlk + c * 32 + el) * NNODES + rowBlk;
        #pragma unroll
        for (int j = 0; j < 4; ++j) {
            float4 v = *(const float4*)&Ts[el * 132 + j * 32 + f4i * 4];
            *(float4*)&out[obase + j * 32 + f4i * 4] = v;
        }
    }
}

// ---- tail: softmax over 3 relation sums ----
__global__ void attout_kernel(float* __restrict__ out) {
    double s0 = g_s[0], s1 = g_s[1], s2 = g_s[2];
    double m = fmax(s0, fmax(s1, s2));
    double e0 = exp(s0 - m), e1 = exp(s1 - m), e2 = exp(s2 - m);
    double inv = 1.0 / (e0 + e1 + e2);
    size_t basei = (size_t)EMB * NNODES;
    out[basei + 0] = (float)(e0 * inv);
    out[basei + 1] = (float)(e1 * inv);
    out[basei + 2] = (float)(e2 * inv);
}

extern "C" void kernel_launch(void* const* d_in, const int* in_sizes, int n_in,
                              void* d_out, int out_size) {
    const float* selfF  = (const float*)d_in[0];
    const float* neighF = (const float*)d_in[1];
    const float* W      = (const float*)d_in[2];
    const float* a      = (const float*)d_in[3];
    float* out = (float*)d_out;

    // one-time host-side sync objects (no device memory; identical work every call)
    static cudaStream_t s2 = nullptr;
    static cudaEvent_t evq[NQ], evj;
    if (s2 == nullptr) {
        cudaStreamCreateWithFlags(&s2, cudaStreamNonBlocking);
        for (int i = 0; i < NQ; ++i)
            cudaEventCreateWithFlags(&evq[i], cudaEventDisableTiming);
        cudaEventCreateWithFlags(&evj, cudaEventDisableTiming);
        cudaFuncSetAttribute(gemm_kernel, cudaFuncAttributeMaxDynamicSharedMemorySize,
                             SM_TOTAL);
    }

    wprep_kernel<<<64, 512>>>(W, a);
    prep2_kernel<<<4, 256>>>();

    // pipelined quarters: mix(q) on default stream, gemm(q) on side stream
    for (int q = 0; q < NQ; ++q) {
        mix_kernel<<<NNODES / NQ / 4, 256>>>(selfF, neighF, q * (NNODES / NQ));
        cudaEventRecord(evq[q], 0);
        cudaStreamWaitEvent(s2, evq[q], 0);
        dim3 gg(EMB / 128, NNODES / NQ / 128);   // (4, 128)
        gemm_kernel<<<gg, 256, SM_TOTAL, s2>>>(out, q * (NNODES / NQ / 128));
    }
    cudaEventRecord(evj, s2);
    cudaStreamWaitEvent(0, evj, 0);

    attout_kernel<<<1, 1>>>(out);
}

// round 13
// speedup vs baseline: 1.5426x; 1.0474x over previous
#include <cuda_runtime.h>
#include <cuda_fp16.h>
#include <cstdint>
#include <math.h>

#define NREL   3
#define NNODES 65536
#define FEAT   512
#define EMB    512
#define BK     32            // k halves per chunk
#define NCHUNK (FEAT/BK)     // 16
#define STAGES 5
#define STAGE_BYTES 20480    // A(10240) + B(10240), stride-40-half rows
#define SM_TOTAL (STAGES * STAGE_BYTES)   // 102400

// ---- scratch (static device globals; no allocations allowed) ----
__device__ __half  g_mixh[(size_t)NNODES * FEAT];  // 67 MB fp16 mixed features
__device__ __half  g_Wh[(size_t)EMB * FEAT];       // fp16 weight copy
__device__ float   g_u[2*EMB];
__device__ float   g_up[64 * 1024];                // prep partials
__device__ double  g_s[NREL];

__device__ __forceinline__ uint32_t smem_u32(const void* p) {
    uint32_t a;
    asm("{ .reg .u64 t; cvta.to.shared.u64 t, %1; cvt.u32.u64 %0, t; }" : "=r"(a) : "l"(p));
    return a;
}

__device__ __forceinline__ void mma_f16(float c[4], const unsigned a[4], const unsigned b[2]) {
    asm volatile(
        "mma.sync.aligned.m16n8k16.row.col.f32.f16.f16.f32 "
        "{%0,%1,%2,%3}, {%4,%5,%6,%7}, {%8,%9}, {%0,%1,%2,%3};\n"
        : "+f"(c[0]), "+f"(c[1]), "+f"(c[2]), "+f"(c[3])
        : "r"(a[0]), "r"(a[1]), "r"(a[2]), "r"(a[3]), "r"(b[0]), "r"(b[1]));
}

__device__ __forceinline__ void ldsm4(unsigned r[4], uint32_t addr) {
    asm volatile("ldmatrix.sync.aligned.m8n8.x4.shared.b16 {%0,%1,%2,%3}, [%4];"
        : "=r"(r[0]), "=r"(r[1]), "=r"(r[2]), "=r"(r[3]) : "r"(addr));
}

__device__ __forceinline__ void cpasync16(uint32_t smem, const void* g) {
    asm volatile("cp.async.cg.shared.global [%0], [%1], 16;" :: "r"(smem), "l"(g));
}
#define CP_COMMIT() asm volatile("cp.async.commit_group;" ::: "memory")
#define CP_WAIT(n)  asm volatile("cp.async.wait_group %0;" :: "n"(n) : "memory")

// ---- kernel 0a: W -> fp16 + partial u sums (8 e-rows per block) ----
__global__ __launch_bounds__(512)
void wprep_kernel(const float* __restrict__ W, const float* __restrict__ a) {
    int f = threadIdx.x;          // 0..511
    int b = blockIdx.x;           // 0..63
    int e0 = b * 8;
    float sc = 0.f, sn = 0.f;
    #pragma unroll
    for (int j = 0; j < 8; ++j) {
        float w = W[(size_t)(e0 + j) * FEAT + f];
        g_Wh[(size_t)(e0 + j) * FEAT + f] = __float2half_rn(w);
        sc += w * a[e0 + j];
        sn += w * a[EMB + e0 + j];
    }
    g_up[b * 1024 + f]       = sc;
    g_up[b * 1024 + 512 + f] = sn;
}

__global__ void prep2_kernel() {
    int i = blockIdx.x * 256 + threadIdx.x;   // 0..1023
    float s = 0.f;
    #pragma unroll
    for (int b = 0; b < 64; ++b) s += g_up[b * 1024 + i];
    g_u[i] = s;
    if (i < NREL) g_s[i] = 0.0;
}

// ---- kernel 1: per-node attention + feature mix (2 warps per node) ----
__global__ __launch_bounds__(256, 5)
void mix_kernel(const float* __restrict__ selfF, const float* __restrict__ neighF) {
    __shared__ float us[2 * EMB];
    __shared__ float dots[4][2][4];
    __shared__ float bs[NREL];

    const int tid  = threadIdx.x;
    const int lane = tid & 31;
    const int wid  = tid >> 5;
    const int nl   = wid >> 1;
    const int half = wid & 1;
    const int n    = blockIdx.x * 4 + nl;

    ((float4*)us)[tid] = ((const float4*)g_u)[tid];
    if (tid < NREL) bs[tid] = 0.f;
    __syncthreads();

    const float4* sp  = (const float4*)(selfF + (size_t)n * FEAT);
    const float4* np0 = (const float4*)(neighF + ((size_t)0 * NNODES + n) * FEAT);
    const float4* np1 = (const float4*)(neighF + ((size_t)1 * NNODES + n) * FEAT);
    const float4* np2 = (const float4*)(neighF + ((size_t)2 * NNODES + n) * FEAT);

    float4 s[2], n0[2], n1[2], n2[2];
    #pragma unroll
    for (int j = 0; j < 2; ++j) {
        int idx = half * 64 + lane + 32 * j;
        s[j]  = sp[idx];
        n0[j] = np0[idx];
        n1[j] = np1[idx];
        n2[j] = np2[idx];
    }

    float ec = 0.f, e0 = 0.f, e1 = 0.f, e2 = 0.f;
    #pragma unroll
    for (int j = 0; j < 2; ++j) {
        int idx = half * 64 + lane + 32 * j;
        float4 uc = ((const float4*)us)[idx];
        float4 un = ((const float4*)us)[128 + idx];
        ec += s[j].x*uc.x + s[j].y*uc.y + s[j].z*uc.z + s[j].w*uc.w;
        e0 += n0[j].x*un.x + n0[j].y*un.y + n0[j].z*un.z + n0[j].w*un.w;
        e1 += n1[j].x*un.x + n1[j].y*un.y + n1[j].z*un.z + n1[j].w*un.w;
        e2 += n2[j].x*un.x + n2[j].y*un.y + n2[j].z*un.z + n2[j].w*un.w;
    }
    #pragma unroll
    for (int o = 16; o; o >>= 1) {
        ec += __shfl_xor_sync(0xffffffffu, ec, o);
        e0 += __shfl_xor_sync(0xffffffffu, e0, o);
        e1 += __shfl_xor_sync(0xffffffffu, e1, o);
        e2 += __shfl_xor_sync(0xffffffffu, e2, o);
    }
    if (lane == 0) {
        dots[nl][half][0] = ec;
        dots[nl][half][1] = e0;
        dots[nl][half][2] = e1;
        dots[nl][half][3] = e2;
    }
    __syncthreads();

    float fec = dots[nl][0][0] + dots[nl][1][0];
    float fe0 = dots[nl][0][1] + dots[nl][1][1];
    float fe1 = dots[nl][0][2] + dots[nl][1][2];
    float fe2 = dots[nl][0][3] + dots[nl][1][3];

    float v0 = fec + fe0, v1 = fec + fe1, v2 = fec + fe2;
    v0 = v0 > 0.f ? v0 : 0.2f * v0;
    v1 = v1 > 0.f ? v1 : 0.2f * v1;
    v2 = v2 > 0.f ? v2 : 0.2f * v2;
    float mx = fmaxf(v0, fmaxf(v1, v2));
    float x0 = expf(v0 - mx), x1 = expf(v1 - mx), x2 = expf(v2 - mx);
    float inv = 1.f / (x0 + x1 + x2);
    float a0 = x0 * inv, a1 = x1 * inv, a2 = x2 * inv;

    uint2* mp = (uint2*)(g_mixh + (size_t)n * FEAT);
    #pragma unroll
    for (int j = 0; j < 2; ++j) {
        int idx = half * 64 + lane + 32 * j;
        float4 m;
        m.x = s[j].x + a0*n0[j].x + a1*n1[j].x + a2*n2[j].x;
        m.y = s[j].y + a0*n0[j].y + a1*n1[j].y + a2*n2[j].y;
        m.z = s[j].z + a0*n0[j].z + a1*n1[j].z + a2*n2[j].z;
        m.w = s[j].w + a0*n0[j].w + a1*n1[j].w + a2*n2[j].w;
        __half2 h0 = __floats2half2_rn(m.x, m.y);
        __half2 h1 = __floats2half2_rn(m.z, m.w);
        uint2 p;
        p.x = *(unsigned*)&h0;  p.y = *(unsigned*)&h1;
        mp[idx] = p;
    }

    if (half == 0 && lane == 0) {
        atomicAdd(&bs[0], a0); atomicAdd(&bs[1], a1); atomicAdd(&bs[2], a2);
    }
    __syncthreads();
    if (tid < NREL) atomicAdd(&g_s[tid], (double)bs[tid]);
}

// ---- kernel 2: fp16 mma.sync GEMM; cp.async 5-stage ring + ldmatrix ----
// out[col][row] = relu( sum_k mix[row][k] * W[col][k] ); 8 warps 2m x 4n.
__global__ void __launch_bounds__(256, 2)
gemm_kernel(float* __restrict__ out) {
    extern __shared__ __align__(16) char sm[];
    const int tid  = threadIdx.x;
    const int wid  = tid >> 5, lane = tid & 31;
    const int wm   = wid >> 2;   // 0..1
    const int wn   = wid & 3;    // 0..3
    const int g    = lane >> 2;
    const int tg   = lane & 3;

    const size_t rowBlk = (size_t)blockIdx.y * 128;   // nodes
    const int    colBlk = blockIdx.x * 128;           // embed
    const __half* Aptr = g_mixh + rowBlk * FEAT;
    const __half* Bp   = g_Wh + (size_t)colBlk * FEAT;

    const uint32_t base = smem_u32(sm);

    const int r0  = tid >> 2;          // 0..63
    const int kq8 = (tid & 3) * 8;
    const uint32_t st0 = (uint32_t)(r0 * 40 + kq8) * 2;
    const uint32_t st1 = st0 + 64 * 40 * 2;

    const uint32_t laneA = (uint32_t)(((lane & 15) * 40 + (lane >> 4) * 8) * 2);
    const uint32_t laneB = (uint32_t)((((lane & 7) + ((lane >> 4) << 3)) * 40
                                       + (((lane >> 3) & 1) << 3)) * 2);

    const __half* gA0 = Aptr + (size_t)r0 * FEAT + kq8;
    const __half* gA1 = Aptr + (size_t)(r0 + 64) * FEAT + kq8;
    const __half* gB0 = Bp   + (size_t)r0 * FEAT + kq8;
    const __half* gB1 = Bp   + (size_t)(r0 + 64) * FEAT + kq8;

    // prologue: issue STAGES-1 chunks
    #pragma unroll
    for (int t = 0; t < STAGES - 1; ++t) {
        uint32_t sA = base + t * STAGE_BYTES;
        uint32_t sB = sA + 10240;
        int k0 = t * BK;
        cpasync16(sA + st0, gA0 + k0);
        cpasync16(sA + st1, gA1 + k0);
        cpasync16(sB + st0, gB0 + k0);
        cpasync16(sB + st1, gB1 + k0);
        CP_COMMIT();
    }

    float acc[4][4][4];
    #pragma unroll
    for (int i = 0; i < 4; ++i)
        #pragma unroll
        for (int j = 0; j < 4; ++j)
            #pragma unroll
            for (int q = 0; q < 4; ++q) acc[i][j][q] = 0.f;

    int slot = 0;
    #pragma unroll 1
    for (int t = 0; t < NCHUNK; ++t) {
        CP_WAIT(STAGES - 2);
        __syncthreads();

        const uint32_t uA = base + slot * STAGE_BYTES;
        const uint32_t uB = uA + 10240;

        #pragma unroll
        for (int kk = 0; kk < 2; ++kk) {
            unsigned af[4][4], bf[4][2];
            #pragma unroll
            for (int mt = 0; mt < 4; ++mt) {
                uint32_t addr = uA + laneA
                              + (uint32_t)((((wm * 64 + mt * 16) * 40) + kk * 16) * 2);
                ldsm4(af[mt], addr);
            }
            #pragma unroll
            for (int p = 0; p < 2; ++p) {
                unsigned r[4];
                uint32_t addr = uB + laneB
                              + (uint32_t)((((wn * 32 + p * 16) * 40) + kk * 16) * 2);
                ldsm4(r, addr);
                bf[2*p  ][0] = r[0];  bf[2*p  ][1] = r[1];
                bf[2*p+1][0] = r[2];  bf[2*p+1][1] = r[3];
            }
            #pragma unroll
            for (int mt = 0; mt < 4; ++mt)
                #pragma unroll
                for (int nt = 0; nt < 4; ++nt)
                    mma_f16(acc[mt][nt], af[mt], bf[nt]);
        }

        // issue chunk t+STAGES-1 into the slot freed by chunk t-1
        const int tn = t + STAGES - 1;
        if (tn < NCHUNK) {
            int ns = slot + (STAGES - 1);  if (ns >= STAGES) ns -= STAGES;
            uint32_t sA = base + ns * STAGE_BYTES;
            uint32_t sB = sA + 10240;
            int k0 = tn * BK;
            cpasync16(sA + st0, gA0 + k0);
            cpasync16(sA + st1, gA1 + k0);
            cpasync16(sB + st0, gB0 + k0);
            cpasync16(sB + st1, gB1 + k0);
        }
        CP_COMMIT();

        if (++slot == STAGES) slot = 0;
    }

    // epilogue: relu + transpose -> out[e][n]; Ts aliases the ring buffer
    float* Ts = (float*)sm;   // 32 x 132
    #pragma unroll 1
    for (int c = 0; c < 4; ++c) {
        __syncthreads();
        if (wn == c) {
            #pragma unroll
            for (int mt = 0; mt < 4; ++mt) {
                #pragma unroll
                for (int nt = 0; nt < 4; ++nt) {
                    int colL = nt * 8 + 2 * tg;
                    int rowL = wm * 64 + mt * 16 + g;
                    float q0 = acc[mt][nt][0], q1 = acc[mt][nt][1];
                    float q2 = acc[mt][nt][2], q3 = acc[mt][nt][3];
                    Ts[(colL    ) * 132 + rowL    ] = q0 > 0.f ? q0 : 0.f;
                    Ts[(colL + 1) * 132 + rowL    ] = q1 > 0.f ? q1 : 0.f;
                    Ts[(colL    ) * 132 + rowL + 8] = q2 > 0.f ? q2 : 0.f;
                    Ts[(colL + 1) * 132 + rowL + 8] = q3 > 0.f ? q3 : 0.f;
                }
            }
        }
        __syncthreads();
        int el  = tid >> 3;
        int f4i = tid & 7;
        size_t obase = (size_t)(colBlk + c * 32 + el) * NNODES + rowBlk;
        #pragma unroll
        for (int j = 0; j < 4; ++j) {
            float4 v = *(const float4*)&Ts[el * 132 + j * 32 + f4i * 4];
            *(float4*)&out[obase + j * 32 + f4i * 4] = v;
        }
    }

    // fused tail: softmax over 3 relation sums (g_s complete: gemm launches
    // after all mix CTAs in-stream)
    if (blockIdx.x == 0 && blockIdx.y == 0 && tid == 0) {
        double s0 = g_s[0], s1 = g_s[1], s2 = g_s[2];
        double m = fmax(s0, fmax(s1, s2));
        double e0 = exp(s0 - m), e1 = exp(s1 - m), e2 = exp(s2 - m);
        double inv = 1.0 / (e0 + e1 + e2);
        size_t obase2 = (size_t)EMB * NNODES;
        out[obase2 + 0] = (float)(e0 * inv);
        out[obase2 + 1] = (float)(e1 * inv);
        out[obase2 + 2] = (float)(e2 * inv);
    }
}

extern "C" void kernel_launch(void* const* d_in, const int* in_sizes, int n_in,
                              void* d_out, int out_size) {
    const float* selfF  = (const float*)d_in[0];
    const float* neighF = (const float*)d_in[1];
    const float* W      = (const float*)d_in[2];
    const float* a      = (const float*)d_in[3];
    float* out = (float*)d_out;

    cudaFuncSetAttribute(gemm_kernel, cudaFuncAttributeMaxDynamicSharedMemorySize, SM_TOTAL);

    wprep_kernel<<<64, 512>>>(W, a);
    prep2_kernel<<<4, 256>>>();
    mix_kernel<<<NNODES / 4, 256>>>(selfF, neighF);

    dim3 ggrid(EMB / 128, NNODES / 128);    // (4, 512)
    gemm_kernel<<<ggrid, 256, SM_TOTAL>>>(out);
}

// round 14
// speedup vs baseline: 1.6174x; 1.0485x over previous
#include <cuda_runtime.h>
#include <cuda_fp16.h>
#include <cstdint>
#include <math.h>

#define NREL   3
#define NNODES 65536
#define FEAT   512
#define EMB    512
#define BK     32            // k halves per chunk
#define NCHUNK (FEAT/BK)     // 16
#define STAGES 5
#define STAGE_BYTES 20480    // A(10240) + B(10240), stride-40-half rows
#define SM_TOTAL (STAGES * STAGE_BYTES)   // 102400

// ---- scratch (static device globals; no allocations allowed) ----
__device__ __half  g_mixh[(size_t)NNODES * FEAT];  // 67 MB fp16 mixed features
__device__ __half  g_Wh[(size_t)EMB * FEAT];       // fp16 weight copy
__device__ float   g_u[2*EMB];
__device__ float   g_up[64 * 1024];                // prep partials
__device__ double  g_s[NREL];

__device__ __forceinline__ uint32_t smem_u32(const void* p) {
    uint32_t a;
    asm("{ .reg .u64 t; cvta.to.shared.u64 t, %1; cvt.u32.u64 %0, t; }" : "=r"(a) : "l"(p));
    return a;
}

__device__ __forceinline__ void mma_f16(float c[4], const unsigned a[4], const unsigned b[2]) {
    asm volatile(
        "mma.sync.aligned.m16n8k16.row.col.f32.f16.f16.f32 "
        "{%0,%1,%2,%3}, {%4,%5,%6,%7}, {%8,%9}, {%0,%1,%2,%3};\n"
        : "+f"(c[0]), "+f"(c[1]), "+f"(c[2]), "+f"(c[3])
        : "r"(a[0]), "r"(a[1]), "r"(a[2]), "r"(a[3]), "r"(b[0]), "r"(b[1]));
}

__device__ __forceinline__ void ldsm4(unsigned r[4], uint32_t addr) {
    asm volatile("ldmatrix.sync.aligned.m8n8.x4.shared.b16 {%0,%1,%2,%3}, [%4];"
        : "=r"(r[0]), "=r"(r[1]), "=r"(r[2]), "=r"(r[3]) : "r"(addr));
}

__device__ __forceinline__ void cpasync16(uint32_t smem, const void* g) {
    asm volatile("cp.async.cg.shared.global [%0], [%1], 16;" :: "r"(smem), "l"(g));
}
#define CP_COMMIT() asm volatile("cp.async.commit_group;" ::: "memory")
#define CP_WAIT(n)  asm volatile("cp.async.wait_group %0;" :: "n"(n) : "memory")

// ---- kernel 0a: W -> fp16 + partial u sums (8 e-rows per block) ----
__global__ __launch_bounds__(512)
void wprep_kernel(const float* __restrict__ W, const float* __restrict__ a) {
    int f = threadIdx.x;          // 0..511
    int b = blockIdx.x;           // 0..63
    int e0 = b * 8;
    float sc = 0.f, sn = 0.f;
    #pragma unroll
    for (int j = 0; j < 8; ++j) {
        float w = W[(size_t)(e0 + j) * FEAT + f];
        g_Wh[(size_t)(e0 + j) * FEAT + f] = __float2half_rn(w);
        sc += w * a[e0 + j];
        sn += w * a[EMB + e0 + j];
    }
    g_up[b * 1024 + f]       = sc;
    g_up[b * 1024 + 512 + f] = sn;
}

__global__ void prep2_kernel() {
    int i = blockIdx.x * 256 + threadIdx.x;   // 0..1023
    float s = 0.f;
    #pragma unroll
    for (int b = 0; b < 64; ++b) s += g_up[b * 1024 + i];
    g_u[i] = s;
    if (i < NREL) g_s[i] = 0.0;
}

// ---- kernel 1: per-node attention + feature mix (2 warps per node) ----
__global__ __launch_bounds__(256, 5)
void mix_kernel(const float* __restrict__ selfF, const float* __restrict__ neighF) {
    __shared__ float us[2 * EMB];
    __shared__ float dots[4][2][4];
    __shared__ float bs[NREL];

    const int tid  = threadIdx.x;
    const int lane = tid & 31;
    const int wid  = tid >> 5;
    const int nl   = wid >> 1;
    const int half = wid & 1;
    const int n    = blockIdx.x * 4 + nl;

    ((float4*)us)[tid] = ((const float4*)g_u)[tid];
    if (tid < NREL) bs[tid] = 0.f;
    __syncthreads();

    const float4* sp  = (const float4*)(selfF + (size_t)n * FEAT);
    const float4* np0 = (const float4*)(neighF + ((size_t)0 * NNODES + n) * FEAT);
    const float4* np1 = (const float4*)(neighF + ((size_t)1 * NNODES + n) * FEAT);
    const float4* np2 = (const float4*)(neighF + ((size_t)2 * NNODES + n) * FEAT);

    float4 s[2], n0[2], n1[2], n2[2];
    #pragma unroll
    for (int j = 0; j < 2; ++j) {
        int idx = half * 64 + lane + 32 * j;
        s[j]  = sp[idx];
        n0[j] = np0[idx];
        n1[j] = np1[idx];
        n2[j] = np2[idx];
    }

    float ec = 0.f, e0 = 0.f, e1 = 0.f, e2 = 0.f;
    #pragma unroll
    for (int j = 0; j < 2; ++j) {
        int idx = half * 64 + lane + 32 * j;
        float4 uc = ((const float4*)us)[idx];
        float4 un = ((const float4*)us)[128 + idx];
        ec += s[j].x*uc.x + s[j].y*uc.y + s[j].z*uc.z + s[j].w*uc.w;
        e0 += n0[j].x*un.x + n0[j].y*un.y + n0[j].z*un.z + n0[j].w*un.w;
        e1 += n1[j].x*un.x + n1[j].y*un.y + n1[j].z*un.z + n1[j].w*un.w;
        e2 += n2[j].x*un.x + n2[j].y*un.y + n2[j].z*un.z + n2[j].w*un.w;
    }
    #pragma unroll
    for (int o = 16; o; o >>= 1) {
        ec += __shfl_xor_sync(0xffffffffu, ec, o);
        e0 += __shfl_xor_sync(0xffffffffu, e0, o);
        e1 += __shfl_xor_sync(0xffffffffu, e1, o);
        e2 += __shfl_xor_sync(0xffffffffu, e2, o);
    }
    if (lane == 0) {
        dots[nl][half][0] = ec;
        dots[nl][half][1] = e0;
        dots[nl][half][2] = e1;
        dots[nl][half][3] = e2;
    }
    __syncthreads();

    float fec = dots[nl][0][0] + dots[nl][1][0];
    float fe0 = dots[nl][0][1] + dots[nl][1][1];
    float fe1 = dots[nl][0][2] + dots[nl][1][2];
    float fe2 = dots[nl][0][3] + dots[nl][1][3];

    float v0 = fec + fe0, v1 = fec + fe1, v2 = fec + fe2;
    v0 = v0 > 0.f ? v0 : 0.2f * v0;
    v1 = v1 > 0.f ? v1 : 0.2f * v1;
    v2 = v2 > 0.f ? v2 : 0.2f * v2;
    float mx = fmaxf(v0, fmaxf(v1, v2));
    float x0 = expf(v0 - mx), x1 = expf(v1 - mx), x2 = expf(v2 - mx);
    float inv = 1.f / (x0 + x1 + x2);
    float a0 = x0 * inv, a1 = x1 * inv, a2 = x2 * inv;

    uint2* mp = (uint2*)(g_mixh + (size_t)n * FEAT);
    #pragma unroll
    for (int j = 0; j < 2; ++j) {
        int idx = half * 64 + lane + 32 * j;
        float4 m;
        m.x = s[j].x + a0*n0[j].x + a1*n1[j].x + a2*n2[j].x;
        m.y = s[j].y + a0*n0[j].y + a1*n1[j].y + a2*n2[j].y;
        m.z = s[j].z + a0*n0[j].z + a1*n1[j].z + a2*n2[j].z;
        m.w = s[j].w + a0*n0[j].w + a1*n1[j].w + a2*n2[j].w;
        __half2 h0 = __floats2half2_rn(m.x, m.y);
        __half2 h1 = __floats2half2_rn(m.z, m.w);
        uint2 p;
        p.x = *(unsigned*)&h0;  p.y = *(unsigned*)&h1;
        mp[idx] = p;
    }

    if (half == 0 && lane == 0) {
        atomicAdd(&bs[0], a0); atomicAdd(&bs[1], a1); atomicAdd(&bs[2], a2);
    }
    __syncthreads();
    if (tid < NREL) atomicAdd(&g_s[tid], (double)bs[tid]);
}

// ---- kernel 2: fp16 mma.sync GEMM; cp.async 5-stage ring + ldmatrix;
//      direct-from-register relu epilogue (no smem staging, no barriers) ----
__global__ void __launch_bounds__(256, 2)
gemm_kernel(float* __restrict__ out) {
    extern __shared__ __align__(16) char sm[];
    const int tid  = threadIdx.x;
    const int wid  = tid >> 5, lane = tid & 31;
    const int wm   = wid >> 2;   // 0..1
    const int wn   = wid & 3;    // 0..3
    const int g    = lane >> 2;
    const int tg   = lane & 3;

    const size_t rowBlk = (size_t)blockIdx.y * 128;   // nodes
    const int    colBlk = blockIdx.x * 128;           // embed
    const __half* Aptr = g_mixh + rowBlk * FEAT;
    const __half* Bp   = g_Wh + (size_t)colBlk * FEAT;

    const uint32_t base = smem_u32(sm);

    const int r0  = tid >> 2;          // 0..63
    const int kq8 = (tid & 3) * 8;
    const uint32_t st0 = (uint32_t)(r0 * 40 + kq8) * 2;
    const uint32_t st1 = st0 + 64 * 40 * 2;

    const uint32_t laneA = (uint32_t)(((lane & 15) * 40 + (lane >> 4) * 8) * 2);
    const uint32_t laneB = (uint32_t)((((lane & 7) + ((lane >> 4) << 3)) * 40
                                       + (((lane >> 3) & 1) << 3)) * 2);

    const __half* gA0 = Aptr + (size_t)r0 * FEAT + kq8;
    const __half* gA1 = Aptr + (size_t)(r0 + 64) * FEAT + kq8;
    const __half* gB0 = Bp   + (size_t)r0 * FEAT + kq8;
    const __half* gB1 = Bp   + (size_t)(r0 + 64) * FEAT + kq8;

    // prologue: issue STAGES-1 chunks
    #pragma unroll
    for (int t = 0; t < STAGES - 1; ++t) {
        uint32_t sA = base + t * STAGE_BYTES;
        uint32_t sB = sA + 10240;
        int k0 = t * BK;
        cpasync16(sA + st0, gA0 + k0);
        cpasync16(sA + st1, gA1 + k0);
        cpasync16(sB + st0, gB0 + k0);
        cpasync16(sB + st1, gB1 + k0);
        CP_COMMIT();
    }

    float acc[4][4][4];
    #pragma unroll
    for (int i = 0; i < 4; ++i)
        #pragma unroll
        for (int j = 0; j < 4; ++j)
            #pragma unroll
            for (int q = 0; q < 4; ++q) acc[i][j][q] = 0.f;

    int slot = 0;
    #pragma unroll 1
    for (int t = 0; t < NCHUNK; ++t) {
        CP_WAIT(STAGES - 2);
        __syncthreads();

        const uint32_t uA = base + slot * STAGE_BYTES;
        const uint32_t uB = uA + 10240;

        #pragma unroll
        for (int kk = 0; kk < 2; ++kk) {
            unsigned af[4][4], bf[4][2];
            #pragma unroll
            for (int mt = 0; mt < 4; ++mt) {
                uint32_t addr = uA + laneA
                              + (uint32_t)((((wm * 64 + mt * 16) * 40) + kk * 16) * 2);
                ldsm4(af[mt], addr);
            }
            #pragma unroll
            for (int p = 0; p < 2; ++p) {
                unsigned r[4];
                uint32_t addr = uB + laneB
                              + (uint32_t)((((wn * 32 + p * 16) * 40) + kk * 16) * 2);
                ldsm4(r, addr);
                bf[2*p  ][0] = r[0];  bf[2*p  ][1] = r[1];
                bf[2*p+1][0] = r[2];  bf[2*p+1][1] = r[3];
            }
            #pragma unroll
            for (int mt = 0; mt < 4; ++mt)
                #pragma unroll
                for (int nt = 0; nt < 4; ++nt)
                    mma_f16(acc[mt][nt], af[mt], bf[nt]);
        }

        // issue chunk t+STAGES-1 into the slot freed by chunk t-1
        const int tn = t + STAGES - 1;
        if (tn < NCHUNK) {
            int ns = slot + (STAGES - 1);  if (ns >= STAGES) ns -= STAGES;
            uint32_t sA = base + ns * STAGE_BYTES;
            uint32_t sB = sA + 10240;
            int k0 = tn * BK;
            cpasync16(sA + st0, gA0 + k0);
            cpasync16(sA + st1, gA1 + k0);
            cpasync16(sB + st0, gB0 + k0);
            cpasync16(sB + st1, gB1 + k0);
        }
        CP_COMMIT();

        if (++slot == STAGES) slot = 0;
    }

    // epilogue: direct relu STG from registers. For fixed (mt,nt,q) the 8
    // g-lanes cover 8 consecutive n -> full 32B sectors; all warps concurrent.
    #pragma unroll
    for (int nt = 0; nt < 4; ++nt) {
        #pragma unroll
        for (int q1 = 0; q1 < 2; ++q1) {           // col = base + q1
            const size_t e = (size_t)(colBlk + wn * 32 + nt * 8 + 2 * tg + q1);
            float* orow = out + e * NNODES + rowBlk + wm * 64 + g;
            #pragma unroll
            for (int mt = 0; mt < 4; ++mt) {
                float v0 = acc[mt][nt][q1];        // row = mt*16 + g
                float v1 = acc[mt][nt][q1 + 2];    // row = mt*16 + g + 8
                orow[mt * 16]     = v0 > 0.f ? v0 : 0.f;
                orow[mt * 16 + 8] = v1 > 0.f ? v1 : 0.f;
            }
        }
    }

    // fused tail: softmax over 3 relation sums (g_s complete: gemm launches
    // after all mix CTAs in-stream)
    if (blockIdx.x == 0 && blockIdx.y == 0 && tid == 0) {
        double s0 = g_s[0], s1 = g_s[1], s2 = g_s[2];
        double m = fmax(s0, fmax(s1, s2));
        double e0 = exp(s0 - m), e1 = exp(s1 - m), e2 = exp(s2 - m);
        double inv = 1.0 / (e0 + e1 + e2);
        size_t obase2 = (size_t)EMB * NNODES;
        out[obase2 + 0] = (float)(e0 * inv);
        out[obase2 + 1] = (float)(e1 * inv);
        out[obase2 + 2] = (float)(e2 * inv);
    }
}

extern "C" void kernel_launch(void* const* d_in, const int* in_sizes, int n_in,
                              void* d_out, int out_size) {
    const float* selfF  = (const float*)d_in[0];
    const float* neighF = (const float*)d_in[1];
    const float* W      = (const float*)d_in[2];
    const float* a      = (const float*)d_in[3];
    float* out = (float*)d_out;

    cudaFuncSetAttribute(gemm_kernel, cudaFuncAttributeMaxDynamicSharedMemorySize, SM_TOTAL);

    wprep_kernel<<<64, 512>>>(W, a);
    prep2_kernel<<<4, 256>>>();
    mix_kernel<<<NNODES / 4, 256>>>(selfF, neighF);

    dim3 ggrid(EMB / 128, NNODES / 128);    // (4, 512)
    gemm_kernel<<<ggrid, 256, SM_TOTAL>>>(out);
}

// round 15
// speedup vs baseline: 1.6735x; 1.0347x over previous
#include <cuda_runtime.h>
#include <cuda_fp16.h>
#include <cstdint>
#include <math.h>

#define NREL   3
#define NNODES 65536
#define FEAT   512
#define EMB    512
#define BK     64            // k halves per chunk
#define NCHUNK (FEAT/BK)     // 8
#define STAGES 3
#define RSTRIDE 72           // halves per smem row (144 B, conflict-free)
#define TILE_BYTES (128 * RSTRIDE * 2)          // 18432 per operand
#define STAGE_BYTES (2 * TILE_BYTES)            // 36864 (A + B)
#define SM_TOTAL (STAGES * STAGE_BYTES)         // 110592

// ---- scratch (static device globals; no allocations allowed) ----
__device__ __half  g_mixh[(size_t)NNODES * FEAT];  // 67 MB fp16 mixed features
__device__ __half  g_Wh[(size_t)EMB * FEAT];       // fp16 weight copy
__device__ float   g_u[2*EMB];
__device__ float   g_up[64 * 1024];                // prep partials
__device__ double  g_s[NREL];

__device__ __forceinline__ uint32_t smem_u32(const void* p) {
    uint32_t a;
    asm("{ .reg .u64 t; cvta.to.shared.u64 t, %1; cvt.u32.u64 %0, t; }" : "=r"(a) : "l"(p));
    return a;
}

__device__ __forceinline__ void mma_f16(float c[4], const unsigned a[4], const unsigned b[2]) {
    asm volatile(
        "mma.sync.aligned.m16n8k16.row.col.f32.f16.f16.f32 "
        "{%0,%1,%2,%3}, {%4,%5,%6,%7}, {%8,%9}, {%0,%1,%2,%3};\n"
        : "+f"(c[0]), "+f"(c[1]), "+f"(c[2]), "+f"(c[3])
        : "r"(a[0]), "r"(a[1]), "r"(a[2]), "r"(a[3]), "r"(b[0]), "r"(b[1]));
}

__device__ __forceinline__ void ldsm4(unsigned r[4], uint32_t addr) {
    asm volatile("ldmatrix.sync.aligned.m8n8.x4.shared.b16 {%0,%1,%2,%3}, [%4];"
        : "=r"(r[0]), "=r"(r[1]), "=r"(r[2]), "=r"(r[3]) : "r"(addr));
}

__device__ __forceinline__ void cpasync16(uint32_t smem, const void* g) {
    asm volatile("cp.async.cg.shared.global [%0], [%1], 16;" :: "r"(smem), "l"(g));
}
#define CP_COMMIT() asm volatile("cp.async.commit_group;" ::: "memory")
#define CP_WAIT(n)  asm volatile("cp.async.wait_group %0;" :: "n"(n) : "memory")

// ---- kernel 0a: W -> fp16 + partial u sums (8 e-rows per block) ----
__global__ __launch_bounds__(512)
void wprep_kernel(const float* __restrict__ W, const float* __restrict__ a) {
    int f = threadIdx.x;          // 0..511
    int b = blockIdx.x;           // 0..63
    int e0 = b * 8;
    float sc = 0.f, sn = 0.f;
    #pragma unroll
    for (int j = 0; j < 8; ++j) {
        float w = W[(size_t)(e0 + j) * FEAT + f];
        g_Wh[(size_t)(e0 + j) * FEAT + f] = __float2half_rn(w);
        sc += w * a[e0 + j];
        sn += w * a[EMB + e0 + j];
    }
    g_up[b * 1024 + f]       = sc;
    g_up[b * 1024 + 512 + f] = sn;
}

__global__ void prep2_kernel() {
    int i = blockIdx.x * 256 + threadIdx.x;   // 0..1023
    float s = 0.f;
    #pragma unroll
    for (int b = 0; b < 64; ++b) s += g_up[b * 1024 + i];
    g_u[i] = s;
    if (i < NREL) g_s[i] = 0.0;
}

// ---- kernel 1: per-node attention + feature mix (2 warps per node) ----
__global__ __launch_bounds__(256, 5)
void mix_kernel(const float* __restrict__ selfF, const float* __restrict__ neighF) {
    __shared__ float us[2 * EMB];
    __shared__ float dots[4][2][4];
    __shared__ float bs[NREL];

    const int tid  = threadIdx.x;
    const int lane = tid & 31;
    const int wid  = tid >> 5;
    const int nl   = wid >> 1;
    const int half = wid & 1;
    const int n    = blockIdx.x * 4 + nl;

    ((float4*)us)[tid] = ((const float4*)g_u)[tid];
    if (tid < NREL) bs[tid] = 0.f;
    __syncthreads();

    const float4* sp  = (const float4*)(selfF + (size_t)n * FEAT);
    const float4* np0 = (const float4*)(neighF + ((size_t)0 * NNODES + n) * FEAT);
    const float4* np1 = (const float4*)(neighF + ((size_t)1 * NNODES + n) * FEAT);
    const float4* np2 = (const float4*)(neighF + ((size_t)2 * NNODES + n) * FEAT);

    float4 s[2], n0[2], n1[2], n2[2];
    #pragma unroll
    for (int j = 0; j < 2; ++j) {
        int idx = half * 64 + lane + 32 * j;
        s[j]  = sp[idx];
        n0[j] = np0[idx];
        n1[j] = np1[idx];
        n2[j] = np2[idx];
    }

    float ec = 0.f, e0 = 0.f, e1 = 0.f, e2 = 0.f;
    #pragma unroll
    for (int j = 0; j < 2; ++j) {
        int idx = half * 64 + lane + 32 * j;
        float4 uc = ((const float4*)us)[idx];
        float4 un = ((const float4*)us)[128 + idx];
        ec += s[j].x*uc.x + s[j].y*uc.y + s[j].z*uc.z + s[j].w*uc.w;
        e0 += n0[j].x*un.x + n0[j].y*un.y + n0[j].z*un.z + n0[j].w*un.w;
        e1 += n1[j].x*un.x + n1[j].y*un.y + n1[j].z*un.z + n1[j].w*un.w;
        e2 += n2[j].x*un.x + n2[j].y*un.y + n2[j].z*un.z + n2[j].w*un.w;
    }
    #pragma unroll
    for (int o = 16; o; o >>= 1) {
        ec += __shfl_xor_sync(0xffffffffu, ec, o);
        e0 += __shfl_xor_sync(0xffffffffu, e0, o);
        e1 += __shfl_xor_sync(0xffffffffu, e1, o);
        e2 += __shfl_xor_sync(0xffffffffu, e2, o);
    }
    if (lane == 0) {
        dots[nl][half][0] = ec;
        dots[nl][half][1] = e0;
        dots[nl][half][2] = e1;
        dots[nl][half][3] = e2;
    }
    __syncthreads();

    float fec = dots[nl][0][0] + dots[nl][1][0];
    float fe0 = dots[nl][0][1] + dots[nl][1][1];
    float fe1 = dots[nl][0][2] + dots[nl][1][2];
    float fe2 = dots[nl][0][3] + dots[nl][1][3];

    float v0 = fec + fe0, v1 = fec + fe1, v2 = fec + fe2;
    v0 = v0 > 0.f ? v0 : 0.2f * v0;
    v1 = v1 > 0.f ? v1 : 0.2f * v1;
    v2 = v2 > 0.f ? v2 : 0.2f * v2;
    float mx = fmaxf(v0, fmaxf(v1, v2));
    float x0 = expf(v0 - mx), x1 = expf(v1 - mx), x2 = expf(v2 - mx);
    float inv = 1.f / (x0 + x1 + x2);
    float a0 = x0 * inv, a1 = x1 * inv, a2 = x2 * inv;

    uint2* mp = (uint2*)(g_mixh + (size_t)n * FEAT);
    #pragma unroll
    for (int j = 0; j < 2; ++j) {
        int idx = half * 64 + lane + 32 * j;
        float4 m;
        m.x = s[j].x + a0*n0[j].x + a1*n1[j].x + a2*n2[j].x;
        m.y = s[j].y + a0*n0[j].y + a1*n1[j].y + a2*n2[j].y;
        m.z = s[j].z + a0*n0[j].z + a1*n1[j].z + a2*n2[j].z;
        m.w = s[j].w + a0*n0[j].w + a1*n1[j].w + a2*n2[j].w;
        __half2 h0 = __floats2half2_rn(m.x, m.y);
        __half2 h1 = __floats2half2_rn(m.z, m.w);
        uint2 p;
        p.x = *(unsigned*)&h0;  p.y = *(unsigned*)&h1;
        mp[idx] = p;
    }

    if (half == 0 && lane == 0) {
        atomicAdd(&bs[0], a0); atomicAdd(&bs[1], a1); atomicAdd(&bs[2], a2);
    }
    __syncthreads();
    if (tid < NREL) atomicAdd(&g_s[tid], (double)bs[tid]);
}

// ---- kernel 2: fp16 mma.sync GEMM; BK=64, 3-stage cp.async ring (110.6 KB),
//      loads issued before compute; direct-register relu epilogue ----
__global__ void __launch_bounds__(256, 2)
gemm_kernel(float* __restrict__ out) {
    extern __shared__ __align__(16) char sm[];
    const int tid  = threadIdx.x;
    const int wid  = tid >> 5, lane = tid & 31;
    const int wm   = wid >> 2;   // 0..1
    const int wn   = wid & 3;    // 0..3
    const int g    = lane >> 2;
    const int tg   = lane & 3;

    const size_t rowBlk = (size_t)blockIdx.y * 128;   // nodes
    const int    colBlk = blockIdx.x * 128;           // embed
    const __half* Aptr = g_mixh + rowBlk * FEAT;
    const __half* Bp   = g_Wh + (size_t)colBlk * FEAT;

    const uint32_t base = smem_u32(sm);

    // per-thread cp.async coords: 1024 granules (16B) per operand tile,
    // 4 per thread: idx = tid + i*256, row = idx>>3, colg = idx&7
    const int r8  = tid >> 3;          // rows for i-th: r8 + i*32
    const int cg8 = (tid & 7) * 8;     // granule half-offset within row

    const __half* gA = Aptr + (size_t)r8 * FEAT + cg8;
    const __half* gB = Bp   + (size_t)r8 * FEAT + cg8;
    const uint32_t stoff = (uint32_t)(r8 * RSTRIDE + cg8) * 2;

    const uint32_t laneA = (uint32_t)(((lane & 15) * RSTRIDE + (lane >> 4) * 8) * 2);
    const uint32_t laneB = (uint32_t)((((lane & 7) + ((lane >> 4) << 3)) * RSTRIDE
                                       + (((lane >> 3) & 1) << 3)) * 2);

    // prologue: issue STAGES-1 = 2 chunks
    #pragma unroll
    for (int t = 0; t < STAGES - 1; ++t) {
        uint32_t sA = base + t * STAGE_BYTES;
        uint32_t sB = sA + TILE_BYTES;
        int k0 = t * BK;
        #pragma unroll
        for (int i = 0; i < 4; ++i) {
            uint32_t rowadd = (uint32_t)(i * 32 * RSTRIDE * 2);
            size_t   gadd   = (size_t)i * 32 * FEAT;
            cpasync16(sA + stoff + rowadd, gA + gadd + k0);
            cpasync16(sB + stoff + rowadd, gB + gadd + k0);
        }
        CP_COMMIT();
    }

    float acc[4][4][4];
    #pragma unroll
    for (int i = 0; i < 4; ++i)
        #pragma unroll
        for (int j = 0; j < 4; ++j)
            #pragma unroll
            for (int q = 0; q < 4; ++q) acc[i][j][q] = 0.f;

    int slot = 0;
    #pragma unroll 1
    for (int t = 0; t < NCHUNK; ++t) {
        CP_WAIT(STAGES - 2);
        __syncthreads();

        const uint32_t uA = base + slot * STAGE_BYTES;
        const uint32_t uB = uA + TILE_BYTES;

        // issue chunk t+2 into the slot freed by chunk t-1 (free after barrier)
        const int tn = t + STAGES - 1;
        if (tn < NCHUNK) {
            int ns = slot + (STAGES - 1);  if (ns >= STAGES) ns -= STAGES;
            uint32_t sA = base + ns * STAGE_BYTES;
            uint32_t sB = sA + TILE_BYTES;
            int k0 = tn * BK;
            #pragma unroll
            for (int i = 0; i < 4; ++i) {
                uint32_t rowadd = (uint32_t)(i * 32 * RSTRIDE * 2);
                size_t   gadd   = (size_t)i * 32 * FEAT;
                cpasync16(sA + stoff + rowadd, gA + gadd + k0);
                cpasync16(sB + stoff + rowadd, gB + gadd + k0);
            }
        }
        CP_COMMIT();

        #pragma unroll
        for (int kk = 0; kk < 4; ++kk) {
            unsigned af[4][4], bf[4][2];
            #pragma unroll
            for (int mt = 0; mt < 4; ++mt) {
                uint32_t addr = uA + laneA
                              + (uint32_t)((((wm * 64 + mt * 16) * RSTRIDE) + kk * 16) * 2);
                ldsm4(af[mt], addr);
            }
            #pragma unroll
            for (int p = 0; p < 2; ++p) {
                unsigned r[4];
                uint32_t addr = uB + laneB
                              + (uint32_t)((((wn * 32 + p * 16) * RSTRIDE) + kk * 16) * 2);
                ldsm4(r, addr);
                bf[2*p  ][0] = r[0];  bf[2*p  ][1] = r[1];
                bf[2*p+1][0] = r[2];  bf[2*p+1][1] = r[3];
            }
            #pragma unroll
            for (int mt = 0; mt < 4; ++mt)
                #pragma unroll
                for (int nt = 0; nt < 4; ++nt)
                    mma_f16(acc[mt][nt], af[mt], bf[nt]);
        }

        if (++slot == STAGES) slot = 0;
    }

    // epilogue: direct relu STG from registers (full 32B sectors per g-octet)
    #pragma unroll
    for (int nt = 0; nt < 4; ++nt) {
        #pragma unroll
        for (int q1 = 0; q1 < 2; ++q1) {
            const size_t e = (size_t)(colBlk + wn * 32 + nt * 8 + 2 * tg + q1);
            float* orow = out + e * NNODES + rowBlk + wm * 64 + g;
            #pragma unroll
            for (int mt = 0; mt < 4; ++mt) {
                float v0 = acc[mt][nt][q1];
                float v1 = acc[mt][nt][q1 + 2];
                orow[mt * 16]     = v0 > 0.f ? v0 : 0.f;
                orow[mt * 16 + 8] = v1 > 0.f ? v1 : 0.f;
            }
        }
    }

    // fused tail: softmax over 3 relation sums
    if (blockIdx.x == 0 && blockIdx.y == 0 && tid == 0) {
        double s0 = g_s[0], s1 = g_s[1], s2 = g_s[2];
        double m = fmax(s0, fmax(s1, s2));
        double e0 = exp(s0 - m), e1 = exp(s1 - m), e2 = exp(s2 - m);
        double inv = 1.0 / (e0 + e1 + e2);
        size_t obase2 = (size_t)EMB * NNODES;
        out[obase2 + 0] = (float)(e0 * inv);
        out[obase2 + 1] = (float)(e1 * inv);
        out[obase2 + 2] = (float)(e2 * inv);
    }
}

extern "C" void kernel_launch(void* const* d_in, const int* in_sizes, int n_in,
                              void* d_out, int out_size) {
    const float* selfF  = (const float*)d_in[0];
    const float* neighF = (const float*)d_in[1];
    const float* W      = (const float*)d_in[2];
    const float* a      = (const float*)d_in[3];
    float* out = (float*)d_out;

    cudaFuncSetAttribute(gemm_kernel, cudaFuncAttributeMaxDynamicSharedMemorySize, SM_TOTAL);

    wprep_kernel<<<64, 512>>>(W, a);
    prep2_kernel<<<4, 256>>>();
    mix_kernel<<<NNODES / 4, 256>>>(selfF, neighF);

    dim3 ggrid(EMB / 128, NNODES / 128);    // (4, 512)
    gemm_kernel<<<ggrid, 256, SM_TOTAL>>>(out);
}

// round 17
// speedup vs baseline: 1.7564x; 1.0496x over previous
#include <cuda_runtime.h>
#include <cuda_fp16.h>
#include <cstdint>
#include <math.h>

#define NREL   3
#define NNODES 65536
#define FEAT   512
#define EMB    512
#define BK     64            // k halves per chunk
#define NCHUNK (FEAT/BK)     // 8
#define STAGES 3
#define RSTRIDE 72           // halves per smem row (144 B, conflict-free)
#define TILE_BYTES (128 * RSTRIDE * 2)          // 18432 per operand
#define STAGE_BYTES (2 * TILE_BYTES)            // 36864 (A + B)
#define RING_BYTES (STAGES * STAGE_BYTES)       // 110592
#define SM_TOTAL (RING_BYTES + 64)              // + mbarriers

// ---- scratch (static device globals; no allocations allowed) ----
__device__ __half  g_mixh[(size_t)NNODES * FEAT];  // 67 MB fp16 mixed features
__device__ __half  g_Wh[(size_t)EMB * FEAT];       // fp16 weight copy
__device__ float   g_u[2*EMB];
__device__ float   g_up[64 * 1024];                // prep partials
__device__ double  g_s[NREL];

__device__ __forceinline__ uint32_t smem_u32(const void* p) {
    uint32_t a;
    asm("{ .reg .u64 t; cvta.to.shared.u64 t, %1; cvt.u32.u64 %0, t; }" : "=r"(a) : "l"(p));
    return a;
}

__device__ __forceinline__ void mma_f16(float c[4], const unsigned a[4], const unsigned b[2]) {
    asm volatile(
        "mma.sync.aligned.m16n8k16.row.col.f32.f16.f16.f32 "
        "{%0,%1,%2,%3}, {%4,%5,%6,%7}, {%8,%9}, {%0,%1,%2,%3};\n"
        : "+f"(c[0]), "+f"(c[1]), "+f"(c[2]), "+f"(c[3])
        : "r"(a[0]), "r"(a[1]), "r"(a[2]), "r"(a[3]), "r"(b[0]), "r"(b[1]));
}

__device__ __forceinline__ void ldsm4(unsigned r[4], uint32_t addr) {
    asm volatile("ldmatrix.sync.aligned.m8n8.x4.shared.b16 {%0,%1,%2,%3}, [%4];"
        : "=r"(r[0]), "=r"(r[1]), "=r"(r[2]), "=r"(r[3]) : "r"(addr));
}

__device__ __forceinline__ void cpasync16(uint32_t smem, const void* g) {
    asm volatile("cp.async.cg.shared.global [%0], [%1], 16;" :: "r"(smem), "l"(g));
}

#define MBAR_INIT(addr, cnt) \
    asm volatile("mbarrier.init.shared.b64 [%0], %1;" :: "r"(addr), "r"((uint32_t)(cnt)) : "memory")
#define MBAR_ARRIVE(addr) \
    asm volatile("mbarrier.arrive.shared.b64 _, [%0];" :: "r"(addr) : "memory")
// .noinc: completion counts against the init arrival count (default variant
// increments expect-count first -> net-zero -> deadlock, as seen in R16)
#define CPASYNC_MBAR_ARRIVE(addr) \
    asm volatile("cp.async.mbarrier.arrive.noinc.shared::cta.b64 [%0];" :: "r"(addr) : "memory")
#define MBAR_WAIT(addr, par) do {                                         \
    uint32_t _m = (addr); uint32_t _p = (par); uint32_t _d;               \
    asm volatile("{\n\t.reg .pred p;\n\t"                                 \
        "mbarrier.try_wait.parity.acquire.cta.shared::cta.b64 p, [%1], %2;\n\t" \
        "selp.b32 %0, 1, 0, p;\n\t}"                                      \
        : "=r"(_d) : "r"(_m), "r"(_p) : "memory");                        \
    if (!_d) {                                                            \
        asm volatile("{\n\t.reg .pred P1;\n\t"                            \
            "WL_%=:\n\t"                                                  \
            "mbarrier.try_wait.parity.acquire.cta.shared::cta.b64 P1, [%0], %1, 0x989680;\n\t" \
            "@P1 bra.uni WD_%=;\n\t"                                      \
            "bra.uni WL_%=;\n\t"                                          \
            "WD_%=:\n\t}" :: "r"(_m), "r"(_p) : "memory");                \
    }                                                                     \
} while (0)

// ---- kernel 0a: W -> fp16 + partial u sums (8 e-rows per block) ----
__global__ __launch_bounds__(512)
void wprep_kernel(const float* __restrict__ W, const float* __restrict__ a) {
    int f = threadIdx.x;          // 0..511
    int b = blockIdx.x;           // 0..63
    int e0 = b * 8;
    float sc = 0.f, sn = 0.f;
    #pragma unroll
    for (int j = 0; j < 8; ++j) {
        float w = W[(size_t)(e0 + j) * FEAT + f];
        g_Wh[(size_t)(e0 + j) * FEAT + f] = __float2half_rn(w);
        sc += w * a[e0 + j];
        sn += w * a[EMB + e0 + j];
    }
    g_up[b * 1024 + f]       = sc;
    g_up[b * 1024 + 512 + f] = sn;
}

__global__ void prep2_kernel() {
    int i = blockIdx.x * 256 + threadIdx.x;   // 0..1023
    float s = 0.f;
    #pragma unroll
    for (int b = 0; b < 64; ++b) s += g_up[b * 1024 + i];
    g_u[i] = s;
    if (i < NREL) g_s[i] = 0.0;
}

// ---- kernel 1: per-node attention + feature mix (2 warps per node) ----
__global__ __launch_bounds__(256, 5)
void mix_kernel(const float* __restrict__ selfF, const float* __restrict__ neighF) {
    __shared__ float us[2 * EMB];
    __shared__ float dots[4][2][4];
    __shared__ float bs[NREL];

    const int tid  = threadIdx.x;
    const int lane = tid & 31;
    const int wid  = tid >> 5;
    const int nl   = wid >> 1;
    const int half = wid & 1;
    const int n    = blockIdx.x * 4 + nl;

    ((float4*)us)[tid] = ((const float4*)g_u)[tid];
    if (tid < NREL) bs[tid] = 0.f;
    __syncthreads();

    const float4* sp  = (const float4*)(selfF + (size_t)n * FEAT);
    const float4* np0 = (const float4*)(neighF + ((size_t)0 * NNODES + n) * FEAT);
    const float4* np1 = (const float4*)(neighF + ((size_t)1 * NNODES + n) * FEAT);
    const float4* np2 = (const float4*)(neighF + ((size_t)2 * NNODES + n) * FEAT);

    float4 s[2], n0[2], n1[2], n2[2];
    #pragma unroll
    for (int j = 0; j < 2; ++j) {
        int idx = half * 64 + lane + 32 * j;
        s[j]  = sp[idx];
        n0[j] = np0[idx];
        n1[j] = np1[idx];
        n2[j] = np2[idx];
    }

    float ec = 0.f, e0 = 0.f, e1 = 0.f, e2 = 0.f;
    #pragma unroll
    for (int j = 0; j < 2; ++j) {
        int idx = half * 64 + lane + 32 * j;
        float4 uc = ((const float4*)us)[idx];
        float4 un = ((const float4*)us)[128 + idx];
        ec += s[j].x*uc.x + s[j].y*uc.y + s[j].z*uc.z + s[j].w*uc.w;
        e0 += n0[j].x*un.x + n0[j].y*un.y + n0[j].z*un.z + n0[j].w*un.w;
        e1 += n1[j].x*un.x + n1[j].y*un.y + n1[j].z*un.z + n1[j].w*un.w;
        e2 += n2[j].x*un.x + n2[j].y*un.y + n2[j].z*un.z + n2[j].w*un.w;
    }
    #pragma unroll
    for (int o = 16; o; o >>= 1) {
        ec += __shfl_xor_sync(0xffffffffu, ec, o);
        e0 += __shfl_xor_sync(0xffffffffu, e0, o);
        e1 += __shfl_xor_sync(0xffffffffu, e1, o);
        e2 += __shfl_xor_sync(0xffffffffu, e2, o);
    }
    if (lane == 0) {
        dots[nl][half][0] = ec;
        dots[nl][half][1] = e0;
        dots[nl][half][2] = e1;
        dots[nl][half][3] = e2;
    }
    __syncthreads();

    float fec = dots[nl][0][0] + dots[nl][1][0];
    float fe0 = dots[nl][0][1] + dots[nl][1][1];
    float fe1 = dots[nl][0][2] + dots[nl][1][2];
    float fe2 = dots[nl][0][3] + dots[nl][1][3];

    float v0 = fec + fe0, v1 = fec + fe1, v2 = fec + fe2;
    v0 = v0 > 0.f ? v0 : 0.2f * v0;
    v1 = v1 > 0.f ? v1 : 0.2f * v1;
    v2 = v2 > 0.f ? v2 : 0.2f * v2;
    float mx = fmaxf(v0, fmaxf(v1, v2));
    float x0 = expf(v0 - mx), x1 = expf(v1 - mx), x2 = expf(v2 - mx);
    float inv = 1.f / (x0 + x1 + x2);
    float a0 = x0 * inv, a1 = x1 * inv, a2 = x2 * inv;

    uint2* mp = (uint2*)(g_mixh + (size_t)n * FEAT);
    #pragma unroll
    for (int j = 0; j < 2; ++j) {
        int idx = half * 64 + lane + 32 * j;
        float4 m;
        m.x = s[j].x + a0*n0[j].x + a1*n1[j].x + a2*n2[j].x;
        m.y = s[j].y + a0*n0[j].y + a1*n1[j].y + a2*n2[j].y;
        m.z = s[j].z + a0*n0[j].z + a1*n1[j].z + a2*n2[j].z;
        m.w = s[j].w + a0*n0[j].w + a1*n1[j].w + a2*n2[j].w;
        __half2 h0 = __floats2half2_rn(m.x, m.y);
        __half2 h1 = __floats2half2_rn(m.z, m.w);
        uint2 p;
        p.x = *(unsigned*)&h0;  p.y = *(unsigned*)&h1;
        mp[idx] = p;
    }

    if (half == 0 && lane == 0) {
        atomicAdd(&bs[0], a0); atomicAdd(&bs[1], a1); atomicAdd(&bs[2], a2);
    }
    __syncthreads();
    if (tid < NREL) atomicAdd(&g_s[tid], (double)bs[tid]);
}

// ---- kernel 2: fp16 mma.sync GEMM; BK=64, 3-stage mbarrier producer/consumer
//      ring (no CTA barriers in the mainloop); direct-register relu epilogue ----
__global__ void __launch_bounds__(256, 2)
gemm_kernel(float* __restrict__ out) {
    extern __shared__ __align__(16) char sm[];
    const int tid  = threadIdx.x;
    const int wid  = tid >> 5, lane = tid & 31;
    const int wm   = wid >> 2;   // 0..1
    const int wn   = wid & 3;    // 0..3
    const int g    = lane >> 2;
    const int tg   = lane & 3;

    const size_t rowBlk = (size_t)blockIdx.y * 128;   // nodes
    const int    colBlk = blockIdx.x * 128;           // embed
    const __half* Aptr = g_mixh + rowBlk * FEAT;
    const __half* Bp   = g_Wh + (size_t)colBlk * FEAT;

    const uint32_t base = smem_u32(sm);
    const uint32_t mb   = base + RING_BYTES;   // full[0..2] @ +0,8,16 ; empty[0..2] @ +24,32,40

    if (tid == 0) {
        #pragma unroll
        for (int s = 0; s < STAGES; ++s) {
            MBAR_INIT(mb + s * 8, 256);
            MBAR_INIT(mb + 24 + s * 8, 256);
        }
    }
    __syncthreads();

    // per-thread cp.async coords
    const int r8  = tid >> 3;          // rows: r8 + i*32
    const int cg8 = (tid & 7) * 8;     // half-offset within row
    const __half* gA = Aptr + (size_t)r8 * FEAT + cg8;
    const __half* gB = Bp   + (size_t)r8 * FEAT + cg8;
    const uint32_t stoff = (uint32_t)(r8 * RSTRIDE + cg8) * 2;

    const uint32_t laneA = (uint32_t)(((lane & 15) * RSTRIDE + (lane >> 4) * 8) * 2);
    const uint32_t laneB = (uint32_t)((((lane & 7) + ((lane >> 4) << 3)) * RSTRIDE
                                       + (((lane >> 3) & 1) << 3)) * 2);

    // prologue: fill stages 0,1
    #pragma unroll
    for (int t = 0; t < STAGES - 1; ++t) {
        uint32_t sA = base + t * STAGE_BYTES;
        uint32_t sB = sA + TILE_BYTES;
        int k0 = t * BK;
        #pragma unroll
        for (int i = 0; i < 4; ++i) {
            uint32_t rowadd = (uint32_t)(i * 32 * RSTRIDE * 2);
            size_t   gadd   = (size_t)i * 32 * FEAT;
            cpasync16(sA + stoff + rowadd, gA + gadd + k0);
            cpasync16(sB + stoff + rowadd, gB + gadd + k0);
        }
        CPASYNC_MBAR_ARRIVE(mb + t * 8);
    }

    float acc[4][4][4];
    #pragma unroll
    for (int i = 0; i < 4; ++i)
        #pragma unroll
        for (int j = 0; j < 4; ++j)
            #pragma unroll
            for (int q = 0; q < 4; ++q) acc[i][j][q] = 0.f;

    #pragma unroll 1
    for (int t = 0; t < NCHUNK; ++t) {
        const int s = t % STAGES;
        const int r = t / STAGES;
        MBAR_WAIT(mb + s * 8, (uint32_t)(r & 1));        // data ready

        const uint32_t uA = base + s * STAGE_BYTES;
        const uint32_t uB = uA + TILE_BYTES;

        #pragma unroll
        for (int kk = 0; kk < 4; ++kk) {
            unsigned af[4][4], bf[4][2];
            #pragma unroll
            for (int mt = 0; mt < 4; ++mt) {
                uint32_t addr = uA + laneA
                              + (uint32_t)((((wm * 64 + mt * 16) * RSTRIDE) + kk * 16) * 2);
                ldsm4(af[mt], addr);
            }
            #pragma unroll
            for (int p = 0; p < 2; ++p) {
                unsigned r4[4];
                uint32_t addr = uB + laneB
                              + (uint32_t)((((wn * 32 + p * 16) * RSTRIDE) + kk * 16) * 2);
                ldsm4(r4, addr);
                bf[2*p  ][0] = r4[0];  bf[2*p  ][1] = r4[1];
                bf[2*p+1][0] = r4[2];  bf[2*p+1][1] = r4[3];
            }
            #pragma unroll
            for (int mt = 0; mt < 4; ++mt)
                #pragma unroll
                for (int nt = 0; nt < 4; ++nt)
                    mma_f16(acc[mt][nt], af[mt], bf[nt]);
        }

        MBAR_ARRIVE(mb + 24 + s * 8);                    // stage consumed

        const int tn = t + STAGES - 1;
        if (tn < NCHUNK) {
            const int sn = tn % STAGES;
            const int rn = tn / STAGES;
            if (rn >= 1)
                MBAR_WAIT(mb + 24 + sn * 8, (uint32_t)((rn - 1) & 1));   // slot free
            uint32_t sA = base + sn * STAGE_BYTES;
            uint32_t sB = sA + TILE_BYTES;
            int k0 = tn * BK;
            #pragma unroll
            for (int i = 0; i < 4; ++i) {
                uint32_t rowadd = (uint32_t)(i * 32 * RSTRIDE * 2);
                size_t   gadd   = (size_t)i * 32 * FEAT;
                cpasync16(sA + stoff + rowadd, gA + gadd + k0);
                cpasync16(sB + stoff + rowadd, gB + gadd + k0);
            }
            CPASYNC_MBAR_ARRIVE(mb + sn * 8);
        }
    }

    // epilogue: direct relu STG from registers (full 32B sectors per g-octet)
    #pragma unroll
    for (int nt = 0; nt < 4; ++nt) {
        #pragma unroll
        for (int q1 = 0; q1 < 2; ++q1) {
            const size_t e = (size_t)(colBlk + wn * 32 + nt * 8 + 2 * tg + q1);
            float* orow = out + e * NNODES + rowBlk + wm * 64 + g;
            #pragma unroll
            for (int mt = 0; mt < 4; ++mt) {
                float v0 = acc[mt][nt][q1];
                float v1 = acc[mt][nt][q1 + 2];
                orow[mt * 16]     = v0 > 0.f ? v0 : 0.f;
                orow[mt * 16 + 8] = v1 > 0.f ? v1 : 0.f;
            }
        }
    }

    // fused tail: softmax over 3 relation sums
    if (blockIdx.x == 0 && blockIdx.y == 0 && tid == 0) {
        double s0 = g_s[0], s1 = g_s[1], s2 = g_s[2];
        double m = fmax(s0, fmax(s1, s2));
        double e0 = exp(s0 - m), e1 = exp(s1 - m), e2 = exp(s2 - m);
        double inv = 1.0 / (e0 + e1 + e2);
        size_t obase2 = (size_t)EMB * NNODES;
        out[obase2 + 0] = (float)(e0 * inv);
        out[obase2 + 1] = (float)(e1 * inv);
        out[obase2 + 2] = (float)(e2 * inv);
    }
}

extern "C" void kernel_launch(void* const* d_in, const int* in_sizes, int n_in,
                              void* d_out, int out_size) {
    const float* selfF  = (const float*)d_in[0];
    const float* neighF = (const float*)d_in[1];
    const float* W      = (const float*)d_in[2];
    const float* a      = (const float*)d_in[3];
    float* out = (float*)d_out;

    cudaFuncSetAttribute(gemm_kernel, cudaFuncAttributeMaxDynamicSharedMemorySize, SM_TOTAL);

    wprep_kernel<<<64, 512>>>(W, a);
    prep2_kernel<<<4, 256>>>();
    mix_kernel<<<NNODES / 4, 256>>>(selfF, neighF);

    dim3 ggrid(EMB / 128, NNODES / 128);    // (4, 512)
    gemm_kernel<<<ggrid, 256, SM_TOTAL>>>(out);
}